// round 12
// baseline (speedup 1.0000x reference)
#include <cuda_runtime.h>
#include <cuda_bf16.h>
#include <cstdint>

#define N_NODES  100000
#define N_EDGES  1200000
#define N_GRAPHS 256
#define SCAN_BLOCKS 98                       // ceil(100000/1024)
#define EDGE_BLOCKS ((N_EDGES + 255) / 256)  // 4688

// ---------------- device scratch (no allocs allowed) ----------------
// Contract: g_deg and g_pool are ZERO on entry to kernel_launch (zero-init on
// load; mlp_kernel re-zeroes them at the end of every run) -> deterministic
// graph replay.
__device__ int   g_deg[N_NODES];
__device__ int   g_rowptr[N_NODES + 1];
__device__ int   g_cur[N_NODES];
__device__ int   g_csr[N_EDGES];
__device__ int   g_bsums[SCAN_BLOCKS];
__device__ __align__(16) float g_h1[N_NODES * 64];
__device__ __align__(16) float g_h2[N_NODES * 64];
__device__ __align__(16) float g_pool[N_GRAPHS * 64];
// split-bf16 packed weights: [layer][plane hi/lo][n=64][stride 68] u32 pairs
__device__ __align__(16) uint32_t g_WB[2][2][64][68];

// ---------------- helpers ----------------
// pack two floats as bf16x2: low half = lo (even k), high half = hi (odd k)
__device__ __forceinline__ uint32_t pack_bf(float lo, float hi) {
    uint32_t r;
    asm("cvt.rn.bf16x2.f32 %0, %1, %2;" : "=r"(r) : "f"(hi), "f"(lo));
    return r;
}
__device__ __forceinline__ float bf_hi(float v) {
    return __bfloat162float(__float2bfloat16_rn(v));
}

#define MMA_BF16(d, a0, a1, a2, a3, b0, b1)                                  \
    asm volatile(                                                            \
        "mma.sync.aligned.m16n8k16.row.col.f32.bf16.bf16.f32 "               \
        "{%0,%1,%2,%3}, {%4,%5,%6,%7}, {%8,%9}, {%0,%1,%2,%3};"              \
        : "+f"((d)[0]), "+f"((d)[1]), "+f"((d)[2]), "+f"((d)[3])             \
        : "r"(a0), "r"(a1), "r"(a2), "r"(a3), "r"(b0), "r"(b1))

// ---------------- kernel 1: degree count + weight split/pack --------------
__global__ void count_kernel(const int* __restrict__ edge,
                             const float* __restrict__ W2l,
                             const float* __restrict__ W2r,
                             const float* __restrict__ W3l,
                             const float* __restrict__ W3r) {
    int b = blockIdx.x;
    if (b < EDGE_BLOCKS) {
        int e = b * 256 + threadIdx.x;
        if (e < N_EDGES) atomicAdd(&g_deg[edge[N_EDGES + e]], 1);
        return;
    }
    // tail block: build g_WB. 16384 entries = 2L x 2P x 64n x 64pairs.
#pragma unroll 4
    for (int j = 0; j < 64; ++j) {
        int idx = j * 256 + threadIdx.x;     // 0..16383
        int m = idx & 63;                    // k-pair
        int n = (idx >> 6) & 63;
        int P = (idx >> 12) & 1;
        int L = idx >> 13;
        const float* Wl = L ? W3l : W2l;
        const float* Wr = L ? W3r : W2r;
        int k0 = 2 * m, k1 = 2 * m + 1;
        float v0 = (k0 < 64) ? Wl[k0 * 64 + n] : Wr[(k0 - 64) * 64 + n];
        float v1 = (k1 < 64) ? Wl[k1 * 64 + n] : Wr[(k1 - 64) * 64 + n];
        uint32_t val;
        if (P == 0) val = pack_bf(v0, v1);
        else        val = pack_bf(v0 - bf_hi(v0), v1 - bf_hi(v1));
        g_WB[L][P][n][m] = val;
    }
}

// ---------------- scan ----------------
__global__ void scan_blocks_kernel() {
    __shared__ int s[1024];
    int tid = threadIdx.x;
    int i = blockIdx.x * 1024 + tid;
    int v = (i < N_NODES) ? g_deg[i] : 0;
    s[tid] = v;
    __syncthreads();
    for (int off = 1; off < 1024; off <<= 1) {
        int t = (tid >= off) ? s[tid - off] : 0;
        __syncthreads();
        s[tid] += t;
        __syncthreads();
    }
    if (i < N_NODES) g_rowptr[i] = s[tid] - v;
    if (tid == 1023) g_bsums[blockIdx.x] = s[1023];
}

__global__ void scan_fused_kernel() {
    __shared__ int s[128];
    int tid = threadIdx.x;
    if (tid < 128) s[tid] = (tid < SCAN_BLOCKS) ? g_bsums[tid] : 0;
    __syncthreads();
    for (int off = 1; off < 128; off <<= 1) {
        int t = (tid < 128 && tid >= off) ? s[tid - off] : 0;
        __syncthreads();
        if (tid < 128) s[tid] += t;
        __syncthreads();
    }
    int boff = (blockIdx.x == 0) ? 0 : s[blockIdx.x - 1];
    int i = blockIdx.x * 1024 + tid;
    if (i < N_NODES) {
        int r = g_rowptr[i] + boff;
        g_rowptr[i] = r;
        g_cur[i] = r;
    }
    if (i == 0) g_rowptr[N_NODES] = N_EDGES;
}

__global__ void fill_kernel(const int* __restrict__ edge) {
    int e = blockIdx.x * blockDim.x + threadIdx.x;
    if (e < N_EDGES) {
        int src = edge[e];
        int dst = edge[N_EDGES + e];
        int pos = atomicAdd(&g_cur[dst], 1);
        g_csr[pos] = src;
    }
}

// ---------------- layer 1: x[100k,8] -> g_h1[100k,64], relu ----------------
#define A8_STRIDE 20
__global__ void sage8_kernel(const float* __restrict__ x,
                             const float* __restrict__ Wl,
                             const float* __restrict__ bias,
                             const float* __restrict__ Wr) {
    __shared__ __align__(16) float sA[128 * A8_STRIDE];
    __shared__ float sB[16 * 64];
    __shared__ float sBias[64];

    const int tid = threadIdx.x;
    if (tid < 128) ((float4*)sB)[tid] = ((const float4*)Wl)[tid];
    else           ((float4*)sB)[tid] = ((const float4*)Wr)[tid - 128];
    if (tid < 64) sBias[tid] = bias[tid];

    const int base = blockIdx.x * 128;
    const float4* x4 = (const float4*)x;

    {
        const int lane = tid & 31;
        const int nodeLocal = (tid >> 5) * 16 + (lane >> 1);
        const int p = lane & 1;
        const int node = base + nodeLocal;
        float4 m  = make_float4(0.f, 0.f, 0.f, 0.f);
        float4 sf = make_float4(0.f, 0.f, 0.f, 0.f);
        if (node < N_NODES) {
            int start = g_rowptr[node], end = g_rowptr[node + 1];
            float4 a0 = make_float4(0.f, 0.f, 0.f, 0.f);
            float4 a1 = make_float4(0.f, 0.f, 0.f, 0.f);
            int e = start;
            for (; e + 1 < end; e += 2) {
                int s0 = g_csr[e], s1 = g_csr[e + 1];
                float4 v0 = x4[s0 * 2 + p];
                float4 v1 = x4[s1 * 2 + p];
                a0.x += v0.x; a0.y += v0.y; a0.z += v0.z; a0.w += v0.w;
                a1.x += v1.x; a1.y += v1.y; a1.z += v1.z; a1.w += v1.w;
            }
            if (e < end) {
                float4 v0 = x4[g_csr[e] * 2 + p];
                a0.x += v0.x; a0.y += v0.y; a0.z += v0.z; a0.w += v0.w;
            }
            float inv = 1.0f / (float)max(end - start, 1);
            m.x = (a0.x + a1.x) * inv; m.y = (a0.y + a1.y) * inv;
            m.z = (a0.z + a1.z) * inv; m.w = (a0.w + a1.w) * inv;
            sf = x4[node * 2 + p];
        }
        *(float4*)&sA[nodeLocal * A8_STRIDE + p * 4]     = m;
        *(float4*)&sA[nodeLocal * A8_STRIDE + 8 + p * 4] = sf;
    }
    __syncthreads();

    const int tn = tid & 15, tm = tid >> 4;
    float acc[8][4];
#pragma unroll
    for (int i = 0; i < 8; ++i)
#pragma unroll
        for (int j = 0; j < 4; ++j) acc[i][j] = sBias[tn * 4 + j];

#pragma unroll
    for (int k = 0; k < 16; ++k) {
        float4 bv = *(const float4*)&sB[k * 64 + tn * 4];
        float a[8];
#pragma unroll
        for (int i = 0; i < 8; ++i) a[i] = sA[(tm * 8 + i) * A8_STRIDE + k];
#pragma unroll
        for (int i = 0; i < 8; ++i) {
            acc[i][0] += a[i] * bv.x;
            acc[i][1] += a[i] * bv.y;
            acc[i][2] += a[i] * bv.z;
            acc[i][3] += a[i] * bv.w;
        }
    }

    float4* hout4 = (float4*)g_h1;
#pragma unroll
    for (int i = 0; i < 8; ++i) {
        int node = base + tm * 8 + i;
        if (node < N_NODES) {
            float4 o;
            o.x = fmaxf(acc[i][0], 0.0f);
            o.y = fmaxf(acc[i][1], 0.0f);
            o.z = fmaxf(acc[i][2], 0.0f);
            o.w = fmaxf(acc[i][3], 0.0f);
            hout4[node * 16 + tn] = o;
        }
    }
}

// ---------------- layers 2/3: split-bf16 mma.sync GEMM --------------------
// Tile 128 nodes, 8 warps, warp owns M=16 rows. A[128 x 128k] (mean|self) as
// hi/lo bf16-pair planes (stride 68 u32). B = g_WB planes in smem. Per warp:
// 8 ksteps x 8 ntiles x 3 terms m16n8k16 mma. D fp32 in regs.
#define ASTR 68
#define SM64_U32 (2 * 128 * ASTR + 2 * 64 * ASTR)   // 26112 u32
#define SM64_BYTES (SM64_U32 * 4)                   // 104448

__global__ void __launch_bounds__(256) sage64_kernel(
        int srcbuf, int wsel,
        const float* __restrict__ bias,
        int do_relu, int fuse_pool,
        const int* __restrict__ batch) {
    extern __shared__ uint32_t sm[];
    uint32_t* uA_hi = sm;                    // [128][68]
    uint32_t* uA_lo = sm + 128 * ASTR;       // [128][68]
    uint32_t* uB_hi = sm + 2 * 128 * ASTR;   // [64][68]
    uint32_t* uB_lo = uB_hi + 64 * ASTR;     // [64][68]

    const float* hin = (srcbuf == 0) ? g_h1 : g_h2;
    float* hout      = (srcbuf == 0) ? g_h2 : g_h1;

    const int tid  = threadIdx.x;
    const int base = blockIdx.x * 128;
    const int warp = tid >> 5, lane = tid & 31;

    // ---- copy both B planes (8704 u32 = 2176 uint4) ----
    {
        const uint4* src = (const uint4*)&g_WB[wsel][0][0][0];
        uint4* dst = (uint4*)uB_hi;
#pragma unroll
        for (int t = 0; t < 9; ++t) {
            int i = tid + t * 256;
            if (i < 2176) dst[i] = src[i];
        }
    }
    __syncthreads();   // B visible to all warps (A is warp-local)

    // ---- gather + self -> A planes (half-warp/node, float4, unroll x4) ----
    {
        const float4* hin4 = (const float4*)hin;
        const int half = lane >> 4, hl = lane & 15;
        for (int it = 0; it < 8; ++it) {
            int row = warp * 16 + it * 2 + half;
            int node = base + row;
            float4 m  = make_float4(0.f, 0.f, 0.f, 0.f);
            float4 sf = make_float4(0.f, 0.f, 0.f, 0.f);
            if (node < N_NODES) {
                int start = g_rowptr[node], end = g_rowptr[node + 1];
                float4 a0 = make_float4(0.f, 0.f, 0.f, 0.f);
                float4 a1 = make_float4(0.f, 0.f, 0.f, 0.f);
                float4 a2 = make_float4(0.f, 0.f, 0.f, 0.f);
                float4 a3 = make_float4(0.f, 0.f, 0.f, 0.f);
                int e = start;
                for (; e + 3 < end; e += 4) {
                    int s0 = g_csr[e],     s1 = g_csr[e + 1];
                    int s2 = g_csr[e + 2], s3 = g_csr[e + 3];
                    float4 v0 = hin4[s0 * 16 + hl];
                    float4 v1 = hin4[s1 * 16 + hl];
                    float4 v2 = hin4[s2 * 16 + hl];
                    float4 v3 = hin4[s3 * 16 + hl];
                    a0.x += v0.x; a0.y += v0.y; a0.z += v0.z; a0.w += v0.w;
                    a1.x += v1.x; a1.y += v1.y; a1.z += v1.z; a1.w += v1.w;
                    a2.x += v2.x; a2.y += v2.y; a2.z += v2.z; a2.w += v2.w;
                    a3.x += v3.x; a3.y += v3.y; a3.z += v3.z; a3.w += v3.w;
                }
                for (; e < end; ++e) {
                    float4 v0 = hin4[g_csr[e] * 16 + hl];
                    a0.x += v0.x; a0.y += v0.y; a0.z += v0.z; a0.w += v0.w;
                }
                float inv = 1.0f / (float)max(end - start, 1);
                m.x = (a0.x + a1.x + a2.x + a3.x) * inv;
                m.y = (a0.y + a1.y + a2.y + a3.y) * inv;
                m.z = (a0.z + a1.z + a2.z + a3.z) * inv;
                m.w = (a0.w + a1.w + a2.w + a3.w) * inv;
                sf = hin4[node * 16 + hl];
            }
            // mean -> k pairs [2hl, 2hl+1]; self -> [32+2hl, 32+2hl+1]
            uint32_t* Ah = uA_hi + row * ASTR;
            uint32_t* Al = uA_lo + row * ASTR;
            Ah[2 * hl]     = pack_bf(m.x, m.y);
            Ah[2 * hl + 1] = pack_bf(m.z, m.w);
            Al[2 * hl]     = pack_bf(m.x - bf_hi(m.x), m.y - bf_hi(m.y));
            Al[2 * hl + 1] = pack_bf(m.z - bf_hi(m.z), m.w - bf_hi(m.w));
            Ah[32 + 2 * hl]     = pack_bf(sf.x, sf.y);
            Ah[32 + 2 * hl + 1] = pack_bf(sf.z, sf.w);
            Al[32 + 2 * hl]     = pack_bf(sf.x - bf_hi(sf.x), sf.y - bf_hi(sf.y));
            Al[32 + 2 * hl + 1] = pack_bf(sf.z - bf_hi(sf.z), sf.w - bf_hi(sf.w));
        }
    }
    __syncwarp();

    // ---- mma: D[16x64] += Ah*Bh + Ah*Bl + Al*Bh ----
    const int g = lane >> 2, t = lane & 3;
    const int wrow = warp * 16;
    float d[8][4];
#pragma unroll
    for (int nt = 0; nt < 8; ++nt)
#pragma unroll
        for (int j = 0; j < 4; ++j) d[nt][j] = 0.0f;

#pragma unroll
    for (int kk = 0; kk < 8; ++kk) {
        int pc = kk * 8;
        const uint32_t* ar = uA_hi + (wrow + g) * ASTR + pc + t;
        uint32_t ah0 = ar[0], ah1 = ar[8 * ASTR], ah2 = ar[4], ah3 = ar[8 * ASTR + 4];
        const uint32_t* al = uA_lo + (wrow + g) * ASTR + pc + t;
        uint32_t al0 = al[0], al1 = al[8 * ASTR], al2 = al[4], al3 = al[8 * ASTR + 4];
#pragma unroll
        for (int nt = 0; nt < 8; ++nt) {
            const uint32_t* bh = uB_hi + (nt * 8 + g) * ASTR + pc + t;
            uint32_t bh0 = bh[0], bh1 = bh[4];
            const uint32_t* bl = uB_lo + (nt * 8 + g) * ASTR + pc + t;
            uint32_t bl0 = bl[0], bl1 = bl[4];
            MMA_BF16(d[nt], ah0, ah1, ah2, ah3, bh0, bh1);
            MMA_BF16(d[nt], ah0, ah1, ah2, ah3, bl0, bl1);
            MMA_BF16(d[nt], al0, al1, al2, al3, bh0, bh1);
        }
    }

    if (!fuse_pool) {
        // ---- store h' (layer 2, relu) ----
        int node0 = base + wrow + g;
        int node1 = node0 + 8;
#pragma unroll
        for (int nt = 0; nt < 8; ++nt) {
            int col = nt * 8 + 2 * t;
            float2 bb = *(const float2*)&bias[col];
            if (node0 < N_NODES) {
                float2 o = make_float2(d[nt][0] + bb.x, d[nt][1] + bb.y);
                if (do_relu) { o.x = fmaxf(o.x, 0.f); o.y = fmaxf(o.y, 0.f); }
                *(float2*)&hout[node0 * 64 + col] = o;
            }
            if (node1 < N_NODES) {
                float2 o = make_float2(d[nt][2] + bb.x, d[nt][3] + bb.y);
                if (do_relu) { o.x = fmaxf(o.x, 0.f); o.y = fmaxf(o.y, 0.f); }
                *(float2*)&hout[node1 * 64 + col] = o;
            }
        }
    } else {
        // ---- layer 3: stage to smem scratch, then run-accumulate pool ----
        __syncthreads();                    // all warps done reading A planes
        float* scr = (float*)sm;            // [128][66] fp32 scratch
        int r0 = wrow + g, r1 = r0 + 8;
#pragma unroll
        for (int nt = 0; nt < 8; ++nt) {
            int col = nt * 8 + 2 * t;
            *(float2*)&scr[r0 * 66 + col] = make_float2(d[nt][0], d[nt][1]);
            *(float2*)&scr[r1 * 66 + col] = make_float2(d[nt][2], d[nt][3]);
        }
        __syncthreads();
        int col = tid & 63;
        int rseg = tid >> 6;                // 0..3, 32 rows each
        float bcol = bias[col];
        int cur = -1;
        float s = 0.0f;
        for (int r = 0; r < 32; ++r) {
            int row = rseg * 32 + r;
            int node = base + row;
            if (node < N_NODES) {
                int b = batch[node];
                if (b != cur) {
                    if (cur >= 0) atomicAdd(&g_pool[cur * 64 + col], s);
                    cur = b;
                    s = 0.0f;
                }
                s += scr[row * 66 + col] + bcol;
            }
        }
        if (cur >= 0) atomicAdd(&g_pool[cur * 64 + col], s);
    }
}

// ---------------- MLP head + state re-zero for next replay ----------------
__global__ void mlp_kernel(const float* __restrict__ Wc1,
                           const float* __restrict__ bc1,
                           const float* __restrict__ Wc2,
                           const float* __restrict__ bc2,
                           float* __restrict__ out) {
    int gr = blockIdx.x * 8 + (threadIdx.x >> 5);
    int lane = threadIdx.x & 31;
    if (gr < N_GRAPHS) {
        float h = bc1[lane];
#pragma unroll
        for (int k = 0; k < 64; ++k)
            h += g_pool[gr * 64 + k] * Wc1[k * 32 + lane];
        h = fmaxf(h, 0.0f);
        float p = h * Wc2[lane];
#pragma unroll
        for (int off = 16; off > 0; off >>= 1)
            p += __shfl_xor_sync(0xffffffffu, p, off);
        if (lane == 0) out[gr] = p + bc2[0];
        g_pool[gr * 64 + 2 * lane]     = 0.0f;
        g_pool[gr * 64 + 2 * lane + 1] = 0.0f;
    }
    int gtid = blockIdx.x * 256 + threadIdx.x;
    for (int i = gtid; i < N_NODES; i += 32 * 256) g_deg[i] = 0;
}

// ---------------- launch ----------------
extern "C" void kernel_launch(void* const* d_in, const int* in_sizes, int n_in,
                              void* d_out, int out_size) {
    const float* x     = (const float*)d_in[0];
    const int*   edge  = (const int*)d_in[1];
    const int*   batch = (const int*)d_in[2];
    const float* W1l = (const float*)d_in[3];
    const float* b1  = (const float*)d_in[4];
    const float* W1r = (const float*)d_in[5];
    const float* W2l = (const float*)d_in[6];
    const float* b2  = (const float*)d_in[7];
    const float* W2r = (const float*)d_in[8];
    const float* W3l = (const float*)d_in[9];
    const float* b3  = (const float*)d_in[10];
    const float* W3r = (const float*)d_in[11];
    const float* Wc1 = (const float*)d_in[12];
    const float* bc1 = (const float*)d_in[13];
    const float* Wc2 = (const float*)d_in[14];
    const float* bc2 = (const float*)d_in[15];
    float* out = (float*)d_out;

    cudaFuncSetAttribute(sage64_kernel,
                         cudaFuncAttributeMaxDynamicSharedMemorySize, SM64_BYTES);

    count_kernel<<<EDGE_BLOCKS + 1, 256>>>(edge, W2l, W2r, W3l, W3r);  // 1
    scan_blocks_kernel<<<SCAN_BLOCKS, 1024>>>();                       // 2
    scan_fused_kernel<<<SCAN_BLOCKS, 1024>>>();                        // 3
    fill_kernel<<<EDGE_BLOCKS, 256>>>(edge);                           // 4

    const int NT = (N_NODES + 127) / 128;   // 782
    sage8_kernel<<<NT, 256>>>(x, W1l, b1, W1r);                              // 5
    sage64_kernel<<<NT, 256, SM64_BYTES>>>(0, 0, b2, 1, 0, batch);           // 6
    sage64_kernel<<<NT, 256, SM64_BYTES>>>(1, 1, b3, 0, 1, batch);           // 7

    mlp_kernel<<<32, 256>>>(Wc1, bc1, Wc2, bc2, out);                  // 8
}

// round 13
// speedup vs baseline: 1.2216x; 1.2216x over previous
#include <cuda_runtime.h>
#include <cuda_bf16.h>

#define N_NODES  100000
#define N_EDGES  1200000
#define N_GRAPHS 256
#define SCAN_BLOCKS 98   // ceil(100000/1024); MUST stay < 148 (co-resident)

// ---------------- device scratch (no allocs allowed) ----------------
// Contract: g_deg, g_pool, g_bar are ZERO on entry to kernel_launch
// (zero-init on module load; scan_kernel re-zeroes g_deg, mlp_kernel
// re-zeroes g_pool and g_bar) -> deterministic graph replay.
__device__ int   g_deg[N_NODES];
__device__ int   g_rowptr[N_NODES + 1];
__device__ int   g_cur[N_NODES];
__device__ int   g_csr[N_EDGES];
__device__ int   g_bsums[SCAN_BLOCKS];
__device__ int   g_bar;
__device__ __align__(16) float g_h1[N_NODES * 64];
__device__ __align__(16) float g_h2[N_NODES * 64];
__device__ __align__(16) float g_pool[N_GRAPHS * 64];

// ---------------- CSR build ----------------
__global__ void count_kernel(const int* __restrict__ edge) {
    int e = blockIdx.x * blockDim.x + threadIdx.x;
    if (e < N_EDGES) {
        int dst = edge[N_EDGES + e];
        atomicAdd(&g_deg[dst], 1);
    }
}

// Fused scan: per-block scan -> grid barrier (all 98 blocks co-resident,
// spin is safe) -> top-level prefix recomputed per block -> final rowptr.
// Also re-zeroes g_deg (last reader) for the next replay.
__global__ void scan_kernel() {
    __shared__ int s[1024];
    __shared__ int s2[128];
    const int tid = threadIdx.x;
    const int i = blockIdx.x * 1024 + tid;

    int v = (i < N_NODES) ? g_deg[i] : 0;
    s[tid] = v;
    __syncthreads();
    for (int off = 1; off < 1024; off <<= 1) {
        int t = (tid >= off) ? s[tid - off] : 0;
        __syncthreads();
        s[tid] += t;
        __syncthreads();
    }
    int local_excl = s[tid] - v;           // kept in register across barrier
    if (tid == 1023) g_bsums[blockIdx.x] = s[1023];

    // grid barrier
    __threadfence();
    __syncthreads();
    if (tid == 0) {
        atomicAdd(&g_bar, 1);
        while (*(volatile int*)&g_bar < SCAN_BLOCKS) { }
    }
    __syncthreads();
    __threadfence();

    // top-level prefix over 98 block sums (recomputed in every block)
    if (tid < 128) s2[tid] = (tid < SCAN_BLOCKS) ? g_bsums[tid] : 0;
    __syncthreads();
    for (int off = 1; off < 128; off <<= 1) {
        int t = (tid < 128 && tid >= off) ? s2[tid - off] : 0;
        __syncthreads();
        if (tid < 128) s2[tid] += t;
        __syncthreads();
    }
    int boff = (blockIdx.x == 0) ? 0 : s2[blockIdx.x - 1];
    if (i < N_NODES) {
        int r = local_excl + boff;
        g_rowptr[i] = r;
        g_cur[i] = r;
        g_deg[i] = 0;                      // reset for next replay
    }
    if (i == 0) g_rowptr[N_NODES] = N_EDGES;
}

__global__ void fill_kernel(const int* __restrict__ edge) {
    int e = blockIdx.x * blockDim.x + threadIdx.x;
    if (e < N_EDGES) {
        int src = edge[e];
        int dst = edge[N_EDGES + e];
        int pos = atomicAdd(&g_cur[dst], 1);
        g_csr[pos] = src;
    }
}

// ---------------- layer 1: x[100k,8] -> g_h1[100k,64], relu ----------------
// 256 threads, 128 nodes. Gather uses ALL 8 warps: 2 lanes/node (p = lane&1
// picks float4 half), 16 nodes/warp, 1 LDG.128 per lane per edge.
#define A8_STRIDE 20   // 80 B rows: 16B-aligned for both p=0 and p=1 stores
__global__ void sage8_kernel(const float* __restrict__ x,
                             const float* __restrict__ Wl,
                             const float* __restrict__ bias,
                             const float* __restrict__ Wr) {
    __shared__ __align__(16) float sA[128 * A8_STRIDE]; // [node][16] mean|self
    __shared__ float sB[16 * 64];    // rows 0..7 = Wl, 8..15 = Wr
    __shared__ float sBias[64];

    const int tid = threadIdx.x;
    if (tid < 128) ((float4*)sB)[tid] = ((const float4*)Wl)[tid];
    else           ((float4*)sB)[tid] = ((const float4*)Wr)[tid - 128];
    if (tid < 64) sBias[tid] = bias[tid];

    const int base = blockIdx.x * 128;
    const float4* x4 = (const float4*)x;

    {
        const int lane = tid & 31;
        const int nodeLocal = (tid >> 5) * 16 + (lane >> 1);
        const int p = lane & 1;
        const int node = base + nodeLocal;
        float4 m  = make_float4(0.f, 0.f, 0.f, 0.f);
        float4 sf = make_float4(0.f, 0.f, 0.f, 0.f);
        if (node < N_NODES) {
            int start = g_rowptr[node], end = g_rowptr[node + 1];
            float4 a0 = make_float4(0.f, 0.f, 0.f, 0.f);
            float4 a1 = make_float4(0.f, 0.f, 0.f, 0.f);
            int e = start;
            for (; e + 1 < end; e += 2) {
                int s0 = g_csr[e], s1 = g_csr[e + 1];
                float4 v0 = x4[s0 * 2 + p];
                float4 v1 = x4[s1 * 2 + p];
                a0.x += v0.x; a0.y += v0.y; a0.z += v0.z; a0.w += v0.w;
                a1.x += v1.x; a1.y += v1.y; a1.z += v1.z; a1.w += v1.w;
            }
            if (e < end) {
                float4 v0 = x4[g_csr[e] * 2 + p];
                a0.x += v0.x; a0.y += v0.y; a0.z += v0.z; a0.w += v0.w;
            }
            float inv = 1.0f / (float)max(end - start, 1);
            m.x = (a0.x + a1.x) * inv; m.y = (a0.y + a1.y) * inv;
            m.z = (a0.z + a1.z) * inv; m.w = (a0.w + a1.w) * inv;
            sf = x4[node * 2 + p];
        }
        *(float4*)&sA[nodeLocal * A8_STRIDE + p * 4]     = m;   // mean cols
        *(float4*)&sA[nodeLocal * A8_STRIDE + 8 + p * 4] = sf;  // self cols
    }
    __syncthreads();

    const int tn = tid & 15, tm = tid >> 4;
    float acc[8][4];
#pragma unroll
    for (int i = 0; i < 8; ++i)
#pragma unroll
        for (int j = 0; j < 4; ++j) acc[i][j] = sBias[tn * 4 + j];

#pragma unroll
    for (int k = 0; k < 16; ++k) {
        float4 bv = *(const float4*)&sB[k * 64 + tn * 4];
        float a[8];
#pragma unroll
        for (int i = 0; i < 8; ++i) a[i] = sA[(tm * 8 + i) * A8_STRIDE + k];
#pragma unroll
        for (int i = 0; i < 8; ++i) {
            acc[i][0] += a[i] * bv.x;
            acc[i][1] += a[i] * bv.y;
            acc[i][2] += a[i] * bv.z;
            acc[i][3] += a[i] * bv.w;
        }
    }

    float4* hout4 = (float4*)g_h1;
#pragma unroll
    for (int i = 0; i < 8; ++i) {
        int node = base + tm * 8 + i;
        if (node < N_NODES) {
            float4 o;
            o.x = fmaxf(acc[i][0], 0.0f);
            o.y = fmaxf(acc[i][1], 0.0f);
            o.z = fmaxf(acc[i][2], 0.0f);
            o.w = fmaxf(acc[i][3], 0.0f);
            hout4[node * 16 + tn] = o;
        }
    }
}

// ---------------- layers 2/3: h[100k,64] -> h'[100k,64] (R8/R11 GEMM) -----
// Warp-autonomous. Both weights resident; warp w owns rows [14w,14w+14).
// fuse_pool: layer 3 skips the h3 store and atomically accumulates per-graph
// sums into g_pool (batch is sorted -> ~1 run per thread).
#define TILE_N64 112
#define A_STRIDE 68   // 272 B rows, 16B-aligned
#define SM64_BYTES ((TILE_N64 * A_STRIDE + 2 * 4096) * 4)   // 63232

__global__ void __launch_bounds__(256) sage64_kernel(
                              int srcbuf,
                              const float* __restrict__ Wl,
                              const float* __restrict__ bias,
                              const float* __restrict__ Wr,
                              int do_relu, int fuse_pool,
                              const int* __restrict__ batch) {
    extern __shared__ float sm64[];
    float* sA  = sm64;                              // [112][68]
    float* sBl = sm64 + TILE_N64 * A_STRIDE;        // [64][64]
    float* sBr = sBl + 4096;                        // [64][64]

    const float* hin = (srcbuf == 0) ? g_h1 : g_h2;
    float* hout      = (srcbuf == 0) ? g_h2 : g_h1;

    const int tid  = threadIdx.x;
    const int base = blockIdx.x * TILE_N64;
    const int warp = tid >> 5, lane = tid & 31;
    const int lr = lane >> 4;        // 0/1: row half within warp's 14 rows
    const int hl = lane & 15;        // col group: cols [hl*4, hl*4+4)

    // ---- weights (only block-wide cooperation; ONE sync) ----
    {
        const float4* Wl4 = (const float4*)Wl;
        const float4* Wr4 = (const float4*)Wr;
        float4* l4 = (float4*)sBl;
        float4* r4 = (float4*)sBr;
#pragma unroll
        for (int t = 0; t < 4; ++t) {
            l4[tid + t * 256] = Wl4[tid + t * 256];
            r4[tid + t * 256] = Wr4[tid + t * 256];
        }
    }
    __syncthreads();

    const float4* hin4 = (const float4*)hin;
    const int rowBase = warp * 14 + lr * 7;

    // ---- gather own rows: half-warp per node, float4 lanes, unroll x4 ----
    for (int it = 0; it < 7; ++it) {
        int nodeLocal = rowBase + it;
        int node = base + nodeLocal;
        float4 m = make_float4(0.f, 0.f, 0.f, 0.f);
        if (node < N_NODES) {
            int start = g_rowptr[node], end = g_rowptr[node + 1];
            float4 a0 = make_float4(0.f, 0.f, 0.f, 0.f);
            float4 a1 = make_float4(0.f, 0.f, 0.f, 0.f);
            float4 a2 = make_float4(0.f, 0.f, 0.f, 0.f);
            float4 a3 = make_float4(0.f, 0.f, 0.f, 0.f);
            int e = start;
            for (; e + 3 < end; e += 4) {
                int s0 = g_csr[e],     s1 = g_csr[e + 1];
                int s2 = g_csr[e + 2], s3 = g_csr[e + 3];
                float4 v0 = hin4[s0 * 16 + hl];
                float4 v1 = hin4[s1 * 16 + hl];
                float4 v2 = hin4[s2 * 16 + hl];
                float4 v3 = hin4[s3 * 16 + hl];
                a0.x += v0.x; a0.y += v0.y; a0.z += v0.z; a0.w += v0.w;
                a1.x += v1.x; a1.y += v1.y; a1.z += v1.z; a1.w += v1.w;
                a2.x += v2.x; a2.y += v2.y; a2.z += v2.z; a2.w += v2.w;
                a3.x += v3.x; a3.y += v3.y; a3.z += v3.z; a3.w += v3.w;
            }
            for (; e < end; ++e) {
                int s0 = g_csr[e];
                float4 v0 = hin4[s0 * 16 + hl];
                a0.x += v0.x; a0.y += v0.y; a0.z += v0.z; a0.w += v0.w;
            }
            float inv = 1.0f / (float)max(end - start, 1);
            m.x = (a0.x + a1.x + a2.x + a3.x) * inv;
            m.y = (a0.y + a1.y + a2.y + a3.y) * inv;
            m.z = (a0.z + a1.z + a2.z + a3.z) * inv;
            m.w = (a0.w + a1.w + a2.w + a3.w) * inv;
        }
        *(float4*)&sA[nodeLocal * A_STRIDE + hl * 4] = m;
    }
    __syncwarp();

    // ---- acc init with bias ----
    float acc[7][4];
    {
        float4 bb = *(const float4*)&bias[hl * 4];
#pragma unroll
        for (int i = 0; i < 7; ++i) {
            acc[i][0] = bb.x; acc[i][1] = bb.y; acc[i][2] = bb.z; acc[i][3] = bb.w;
        }
    }

    // ---- GEMM1: acc += mean @ Wl (warp-local A rows) ----
#pragma unroll 4
    for (int k = 0; k < 64; k += 2) {
        float4 bv0 = *(const float4*)&sBl[k * 64 + hl * 4];
        float4 bv1 = *(const float4*)&sBl[(k + 1) * 64 + hl * 4];
        float2 a[7];
#pragma unroll
        for (int i = 0; i < 7; ++i)
            a[i] = *(const float2*)&sA[(rowBase + i) * A_STRIDE + k];
#pragma unroll
        for (int i = 0; i < 7; ++i) {
            acc[i][0] += a[i].x * bv0.x; acc[i][1] += a[i].x * bv0.y;
            acc[i][2] += a[i].x * bv0.z; acc[i][3] += a[i].x * bv0.w;
            acc[i][0] += a[i].y * bv1.x; acc[i][1] += a[i].y * bv1.y;
            acc[i][2] += a[i].y * bv1.z; acc[i][3] += a[i].y * bv1.w;
        }
    }
    __syncwarp();

    // ---- self-fill own 14 rows ----
#pragma unroll
    for (int t = 0; t < 7; ++t) {
        int idx = lane + t * 32;          // 0..223 over 14 rows x 16 cols
        int nl = idx >> 4, c = idx & 15;
        int nodeLocal = warp * 14 + nl;
        int node = base + nodeLocal;
        float4 v = make_float4(0.f, 0.f, 0.f, 0.f);
        if (node < N_NODES) v = hin4[node * 16 + c];
        *(float4*)&sA[nodeLocal * A_STRIDE + c * 4] = v;
    }
    __syncwarp();

    // ---- GEMM2: acc += self @ Wr ----
#pragma unroll 4
    for (int k = 0; k < 64; k += 2) {
        float4 bv0 = *(const float4*)&sBr[k * 64 + hl * 4];
        float4 bv1 = *(const float4*)&sBr[(k + 1) * 64 + hl * 4];
        float2 a[7];
#pragma unroll
        for (int i = 0; i < 7; ++i)
            a[i] = *(const float2*)&sA[(rowBase + i) * A_STRIDE + k];
#pragma unroll
        for (int i = 0; i < 7; ++i) {
            acc[i][0] += a[i].x * bv0.x; acc[i][1] += a[i].x * bv0.y;
            acc[i][2] += a[i].x * bv0.z; acc[i][3] += a[i].x * bv0.w;
            acc[i][0] += a[i].y * bv1.x; acc[i][1] += a[i].y * bv1.y;
            acc[i][2] += a[i].y * bv1.z; acc[i][3] += a[i].y * bv1.w;
        }
    }

    if (!fuse_pool) {
        // ---- store h' ----
        float4* hout4 = (float4*)hout;
#pragma unroll
        for (int i = 0; i < 7; ++i) {
            int node = base + rowBase + i;
            if (node < N_NODES) {
                float4 o;
                o.x = acc[i][0]; o.y = acc[i][1]; o.z = acc[i][2]; o.w = acc[i][3];
                if (do_relu) {
                    o.x = fmaxf(o.x, 0.f); o.y = fmaxf(o.y, 0.f);
                    o.z = fmaxf(o.z, 0.f); o.w = fmaxf(o.w, 0.f);
                }
                hout4[node * 16 + hl] = o;
            }
        }
    } else {
        // ---- layer 3: pool directly (batch sorted -> run-accumulate) ----
        int cur = -1;
        float4 s = make_float4(0.f, 0.f, 0.f, 0.f);
#pragma unroll
        for (int i = 0; i < 7; ++i) {
            int node = base + rowBase + i;
            if (node < N_NODES) {
                int b = batch[node];
                if (b != cur) {
                    if (cur >= 0) {
                        float* dst = &g_pool[cur * 64 + hl * 4];
                        atomicAdd(dst + 0, s.x);
                        atomicAdd(dst + 1, s.y);
                        atomicAdd(dst + 2, s.z);
                        atomicAdd(dst + 3, s.w);
                    }
                    cur = b;
                    s = make_float4(0.f, 0.f, 0.f, 0.f);
                }
                s.x += acc[i][0]; s.y += acc[i][1];
                s.z += acc[i][2]; s.w += acc[i][3];
            }
        }
        if (cur >= 0) {
            float* dst = &g_pool[cur * 64 + hl * 4];
            atomicAdd(dst + 0, s.x);
            atomicAdd(dst + 1, s.y);
            atomicAdd(dst + 2, s.z);
            atomicAdd(dst + 3, s.w);
        }
    }
}

// ---------------- MLP head + state re-zero for next replay ----------------
__global__ void mlp_kernel(const float* __restrict__ Wc1,
                           const float* __restrict__ bc1,
                           const float* __restrict__ Wc2,
                           const float* __restrict__ bc2,
                           float* __restrict__ out) {
    int gr = blockIdx.x * 8 + (threadIdx.x >> 5);
    int lane = threadIdx.x & 31;
    if (gr < N_GRAPHS) {
        float h = bc1[lane];
#pragma unroll
        for (int k = 0; k < 64; ++k)
            h += g_pool[gr * 64 + k] * Wc1[k * 32 + lane];
        h = fmaxf(h, 0.0f);
        float p = h * Wc2[lane];
#pragma unroll
        for (int off = 16; off > 0; off >>= 1)
            p += __shfl_xor_sync(0xffffffffu, p, off);
        if (lane == 0) out[gr] = p + bc2[0];
        // zero own pool row for next replay (reads above are complete)
        g_pool[gr * 64 + 2 * lane]     = 0.0f;
        g_pool[gr * 64 + 2 * lane + 1] = 0.0f;
    }
    if (blockIdx.x == 0 && threadIdx.x == 0) g_bar = 0;  // reset scan barrier
}

// ---------------- launch ----------------
extern "C" void kernel_launch(void* const* d_in, const int* in_sizes, int n_in,
                              void* d_out, int out_size) {
    const float* x     = (const float*)d_in[0];
    const int*   edge  = (const int*)d_in[1];     // int32 (JAX x64 disabled)
    const int*   batch = (const int*)d_in[2];     // int32
    const float* W1l = (const float*)d_in[3];
    const float* b1  = (const float*)d_in[4];
    const float* W1r = (const float*)d_in[5];
    const float* W2l = (const float*)d_in[6];
    const float* b2  = (const float*)d_in[7];
    const float* W2r = (const float*)d_in[8];
    const float* W3l = (const float*)d_in[9];
    const float* b3  = (const float*)d_in[10];
    const float* W3r = (const float*)d_in[11];
    const float* Wc1 = (const float*)d_in[12];
    const float* bc1 = (const float*)d_in[13];
    const float* Wc2 = (const float*)d_in[14];
    const float* bc2 = (const float*)d_in[15];
    float* out = (float*)d_out;

    cudaFuncSetAttribute(sage64_kernel,
                         cudaFuncAttributeMaxDynamicSharedMemorySize, SM64_BYTES);

    count_kernel<<<(N_EDGES + 255) / 256, 256>>>(edge);            // 1
    scan_kernel<<<SCAN_BLOCKS, 1024>>>();                          // 2 (fused)
    fill_kernel<<<(N_EDGES + 255) / 256, 256>>>(edge);             // 3

    const int NT8  = (N_NODES + 127) / 128;                // 782
    const int NT64 = (N_NODES + TILE_N64 - 1) / TILE_N64;  // 893
    sage8_kernel<<<NT8, 256>>>(x, W1l, b1, W1r);                             // 4
    sage64_kernel<<<NT64, 256, SM64_BYTES>>>(0, W2l, b2, W2r, 1, 0, batch);  // 5
    sage64_kernel<<<NT64, 256, SM64_BYTES>>>(1, W3l, b3, W3r, 0, 1, batch);  // 6

    mlp_kernel<<<32, 256>>>(Wc1, bc1, Wc2, bc2, out);              // 7
}

// round 14
// speedup vs baseline: 1.2265x; 1.0041x over previous
#include <cuda_runtime.h>
#include <cuda_bf16.h>

#define N_NODES  100000
#define N_EDGES  1200000
#define N_GRAPHS 256
#define SCAN_BLOCKS 98   // ceil(100000/1024); MUST stay < 148 (co-resident)

// ---------------- device scratch (no allocs allowed) ----------------
// Contract: g_deg, g_pool, g_bar are ZERO on entry to kernel_launch
// (zero-init on module load; scan_kernel re-zeroes g_deg, mlp_kernel
// re-zeroes g_pool and g_bar) -> deterministic graph replay.
__device__ int   g_deg[N_NODES];
__device__ int   g_rowptr[N_NODES + 1];
__device__ int   g_cur[N_NODES];
__device__ int   g_csr[N_EDGES];
__device__ int   g_bsums[SCAN_BLOCKS];
__device__ int   g_bar;
__device__ __align__(16) float g_h1[N_NODES * 64];
__device__ __align__(16) float g_h2[N_NODES * 64];
__device__ __align__(16) float g_pool[N_GRAPHS * 64];

// ---------------- CSR build ----------------
__global__ void count_kernel(const int* __restrict__ edge) {
    int e = blockIdx.x * blockDim.x + threadIdx.x;
    if (e < N_EDGES) {
        int dst = edge[N_EDGES + e];
        atomicAdd(&g_deg[dst], 1);
    }
}

// Fused scan: per-block scan -> grid barrier (all 98 blocks co-resident,
// spin is safe) -> top-level prefix recomputed per block -> final rowptr.
// Also re-zeroes g_deg (last reader) for the next replay.
__global__ void scan_kernel() {
    __shared__ int s[1024];
    __shared__ int s2[128];
    const int tid = threadIdx.x;
    const int i = blockIdx.x * 1024 + tid;

    int v = (i < N_NODES) ? g_deg[i] : 0;
    s[tid] = v;
    __syncthreads();
    for (int off = 1; off < 1024; off <<= 1) {
        int t = (tid >= off) ? s[tid - off] : 0;
        __syncthreads();
        s[tid] += t;
        __syncthreads();
    }
    int local_excl = s[tid] - v;           // kept in register across barrier
    if (tid == 1023) g_bsums[blockIdx.x] = s[1023];

    // grid barrier
    __threadfence();
    __syncthreads();
    if (tid == 0) {
        atomicAdd(&g_bar, 1);
        while (*(volatile int*)&g_bar < SCAN_BLOCKS) { }
    }
    __syncthreads();
    __threadfence();

    // top-level prefix over 98 block sums (recomputed in every block)
    if (tid < 128) s2[tid] = (tid < SCAN_BLOCKS) ? g_bsums[tid] : 0;
    __syncthreads();
    for (int off = 1; off < 128; off <<= 1) {
        int t = (tid < 128 && tid >= off) ? s2[tid - off] : 0;
        __syncthreads();
        if (tid < 128) s2[tid] += t;
        __syncthreads();
    }
    int boff = (blockIdx.x == 0) ? 0 : s2[blockIdx.x - 1];
    if (i < N_NODES) {
        int r = local_excl + boff;
        g_rowptr[i] = r;
        g_cur[i] = r;
        g_deg[i] = 0;                      // reset for next replay
    }
    if (i == 0) g_rowptr[N_NODES] = N_EDGES;
}

__global__ void fill_kernel(const int* __restrict__ edge) {
    int e = blockIdx.x * blockDim.x + threadIdx.x;
    if (e < N_EDGES) {
        int src = edge[e];
        int dst = edge[N_EDGES + e];
        int pos = atomicAdd(&g_cur[dst], 1);
        g_csr[pos] = src;
    }
}

// ---------------- layer 1: x[100k,8] -> g_h1[100k,64], relu ----------------
// 256 threads, 128 nodes. Gather uses ALL 8 warps: 2 lanes/node (p = lane&1
// picks float4 half), 16 nodes/warp, edge loop unrolled x4 (4 LDG.128/lane).
#define A8_STRIDE 20   // 80 B rows: 16B-aligned for both p=0 and p=1 stores
__global__ void sage8_kernel(const float* __restrict__ x,
                             const float* __restrict__ Wl,
                             const float* __restrict__ bias,
                             const float* __restrict__ Wr) {
    __shared__ __align__(16) float sA[128 * A8_STRIDE]; // [node][16] mean|self
    __shared__ float sB[16 * 64];    // rows 0..7 = Wl, 8..15 = Wr
    __shared__ float sBias[64];

    const int tid = threadIdx.x;
    if (tid < 128) ((float4*)sB)[tid] = ((const float4*)Wl)[tid];
    else           ((float4*)sB)[tid] = ((const float4*)Wr)[tid - 128];
    if (tid < 64) sBias[tid] = bias[tid];

    const int base = blockIdx.x * 128;
    const float4* x4 = (const float4*)x;

    {
        const int lane = tid & 31;
        const int nodeLocal = (tid >> 5) * 16 + (lane >> 1);
        const int p = lane & 1;
        const int node = base + nodeLocal;
        float4 m  = make_float4(0.f, 0.f, 0.f, 0.f);
        float4 sf = make_float4(0.f, 0.f, 0.f, 0.f);
        if (node < N_NODES) {
            int start = g_rowptr[node], end = g_rowptr[node + 1];
            float4 a0 = make_float4(0.f, 0.f, 0.f, 0.f);
            float4 a1 = make_float4(0.f, 0.f, 0.f, 0.f);
            float4 a2 = make_float4(0.f, 0.f, 0.f, 0.f);
            float4 a3 = make_float4(0.f, 0.f, 0.f, 0.f);
            int e = start;
            for (; e + 3 < end; e += 4) {
                int s0 = g_csr[e],     s1 = g_csr[e + 1];
                int s2 = g_csr[e + 2], s3 = g_csr[e + 3];
                float4 v0 = x4[s0 * 2 + p];
                float4 v1 = x4[s1 * 2 + p];
                float4 v2 = x4[s2 * 2 + p];
                float4 v3 = x4[s3 * 2 + p];
                a0.x += v0.x; a0.y += v0.y; a0.z += v0.z; a0.w += v0.w;
                a1.x += v1.x; a1.y += v1.y; a1.z += v1.z; a1.w += v1.w;
                a2.x += v2.x; a2.y += v2.y; a2.z += v2.z; a2.w += v2.w;
                a3.x += v3.x; a3.y += v3.y; a3.z += v3.z; a3.w += v3.w;
            }
            for (; e < end; ++e) {
                float4 v0 = x4[g_csr[e] * 2 + p];
                a0.x += v0.x; a0.y += v0.y; a0.z += v0.z; a0.w += v0.w;
            }
            float inv = 1.0f / (float)max(end - start, 1);
            m.x = (a0.x + a1.x + a2.x + a3.x) * inv;
            m.y = (a0.y + a1.y + a2.y + a3.y) * inv;
            m.z = (a0.z + a1.z + a2.z + a3.z) * inv;
            m.w = (a0.w + a1.w + a2.w + a3.w) * inv;
            sf = x4[node * 2 + p];
        }
        *(float4*)&sA[nodeLocal * A8_STRIDE + p * 4]     = m;   // mean cols
        *(float4*)&sA[nodeLocal * A8_STRIDE + 8 + p * 4] = sf;  // self cols
    }
    __syncthreads();

    const int tn = tid & 15, tm = tid >> 4;
    float acc[8][4];
#pragma unroll
    for (int i = 0; i < 8; ++i)
#pragma unroll
        for (int j = 0; j < 4; ++j) acc[i][j] = sBias[tn * 4 + j];

#pragma unroll
    for (int k = 0; k < 16; ++k) {
        float4 bv = *(const float4*)&sB[k * 64 + tn * 4];
        float a[8];
#pragma unroll
        for (int i = 0; i < 8; ++i) a[i] = sA[(tm * 8 + i) * A8_STRIDE + k];
#pragma unroll
        for (int i = 0; i < 8; ++i) {
            acc[i][0] += a[i] * bv.x;
            acc[i][1] += a[i] * bv.y;
            acc[i][2] += a[i] * bv.z;
            acc[i][3] += a[i] * bv.w;
        }
    }

    float4* hout4 = (float4*)g_h1;
#pragma unroll
    for (int i = 0; i < 8; ++i) {
        int node = base + tm * 8 + i;
        if (node < N_NODES) {
            float4 o;
            o.x = fmaxf(acc[i][0], 0.0f);
            o.y = fmaxf(acc[i][1], 0.0f);
            o.z = fmaxf(acc[i][2], 0.0f);
            o.w = fmaxf(acc[i][3], 0.0f);
            hout4[node * 16 + tn] = o;
        }
    }
}

// ---------------- layers 2/3: h[100k,64] -> h'[100k,64] (R8/R11 GEMM) -----
// Warp-autonomous. Both weights resident; warp w owns rows [14w,14w+14).
// fuse_pool: layer 3 skips the h3 store and atomically accumulates per-graph
// sums into g_pool (batch is sorted -> ~1 run per thread).
#define TILE_N64 112
#define A_STRIDE 68   // 272 B rows, 16B-aligned
#define SM64_BYTES ((TILE_N64 * A_STRIDE + 2 * 4096) * 4)   // 63232

__global__ void __launch_bounds__(256) sage64_kernel(
                              int srcbuf,
                              const float* __restrict__ Wl,
                              const float* __restrict__ bias,
                              const float* __restrict__ Wr,
                              int do_relu, int fuse_pool,
                              const int* __restrict__ batch) {
    extern __shared__ float sm64[];
    float* sA  = sm64;                              // [112][68]
    float* sBl = sm64 + TILE_N64 * A_STRIDE;        // [64][64]
    float* sBr = sBl + 4096;                        // [64][64]

    const float* hin = (srcbuf == 0) ? g_h1 : g_h2;
    float* hout      = (srcbuf == 0) ? g_h2 : g_h1;

    const int tid  = threadIdx.x;
    const int base = blockIdx.x * TILE_N64;
    const int warp = tid >> 5, lane = tid & 31;
    const int lr = lane >> 4;        // 0/1: row half within warp's 14 rows
    const int hl = lane & 15;        // col group: cols [hl*4, hl*4+4)

    // ---- weights (only block-wide cooperation; ONE sync) ----
    {
        const float4* Wl4 = (const float4*)Wl;
        const float4* Wr4 = (const float4*)Wr;
        float4* l4 = (float4*)sBl;
        float4* r4 = (float4*)sBr;
#pragma unroll
        for (int t = 0; t < 4; ++t) {
            l4[tid + t * 256] = Wl4[tid + t * 256];
            r4[tid + t * 256] = Wr4[tid + t * 256];
        }
    }
    __syncthreads();

    const float4* hin4 = (const float4*)hin;
    const int rowBase = warp * 14 + lr * 7;

    // ---- gather own rows: half-warp per node, float4 lanes, unroll x4 ----
    for (int it = 0; it < 7; ++it) {
        int nodeLocal = rowBase + it;
        int node = base + nodeLocal;
        float4 m = make_float4(0.f, 0.f, 0.f, 0.f);
        if (node < N_NODES) {
            int start = g_rowptr[node], end = g_rowptr[node + 1];
            float4 a0 = make_float4(0.f, 0.f, 0.f, 0.f);
            float4 a1 = make_float4(0.f, 0.f, 0.f, 0.f);
            float4 a2 = make_float4(0.f, 0.f, 0.f, 0.f);
            float4 a3 = make_float4(0.f, 0.f, 0.f, 0.f);
            int e = start;
            for (; e + 3 < end; e += 4) {
                int s0 = g_csr[e],     s1 = g_csr[e + 1];
                int s2 = g_csr[e + 2], s3 = g_csr[e + 3];
                float4 v0 = hin4[s0 * 16 + hl];
                float4 v1 = hin4[s1 * 16 + hl];
                float4 v2 = hin4[s2 * 16 + hl];
                float4 v3 = hin4[s3 * 16 + hl];
                a0.x += v0.x; a0.y += v0.y; a0.z += v0.z; a0.w += v0.w;
                a1.x += v1.x; a1.y += v1.y; a1.z += v1.z; a1.w += v1.w;
                a2.x += v2.x; a2.y += v2.y; a2.z += v2.z; a2.w += v2.w;
                a3.x += v3.x; a3.y += v3.y; a3.z += v3.z; a3.w += v3.w;
            }
            for (; e < end; ++e) {
                int s0 = g_csr[e];
                float4 v0 = hin4[s0 * 16 + hl];
                a0.x += v0.x; a0.y += v0.y; a0.z += v0.z; a0.w += v0.w;
            }
            float inv = 1.0f / (float)max(end - start, 1);
            m.x = (a0.x + a1.x + a2.x + a3.x) * inv;
            m.y = (a0.y + a1.y + a2.y + a3.y) * inv;
            m.z = (a0.z + a1.z + a2.z + a3.z) * inv;
            m.w = (a0.w + a1.w + a2.w + a3.w) * inv;
        }
        *(float4*)&sA[nodeLocal * A_STRIDE + hl * 4] = m;
    }
    __syncwarp();

    // ---- acc init with bias ----
    float acc[7][4];
    {
        float4 bb = *(const float4*)&bias[hl * 4];
#pragma unroll
        for (int i = 0; i < 7; ++i) {
            acc[i][0] = bb.x; acc[i][1] = bb.y; acc[i][2] = bb.z; acc[i][3] = bb.w;
        }
    }

    // ---- GEMM1: acc += mean @ Wl (warp-local A rows) ----
#pragma unroll 4
    for (int k = 0; k < 64; k += 2) {
        float4 bv0 = *(const float4*)&sBl[k * 64 + hl * 4];
        float4 bv1 = *(const float4*)&sBl[(k + 1) * 64 + hl * 4];
        float2 a[7];
#pragma unroll
        for (int i = 0; i < 7; ++i)
            a[i] = *(const float2*)&sA[(rowBase + i) * A_STRIDE + k];
#pragma unroll
        for (int i = 0; i < 7; ++i) {
            acc[i][0] += a[i].x * bv0.x; acc[i][1] += a[i].x * bv0.y;
            acc[i][2] += a[i].x * bv0.z; acc[i][3] += a[i].x * bv0.w;
            acc[i][0] += a[i].y * bv1.x; acc[i][1] += a[i].y * bv1.y;
            acc[i][2] += a[i].y * bv1.z; acc[i][3] += a[i].y * bv1.w;
        }
    }
    __syncwarp();

    // ---- self-fill own 14 rows ----
#pragma unroll
    for (int t = 0; t < 7; ++t) {
        int idx = lane + t * 32;          // 0..223 over 14 rows x 16 cols
        int nl = idx >> 4, c = idx & 15;
        int nodeLocal = warp * 14 + nl;
        int node = base + nodeLocal;
        float4 v = make_float4(0.f, 0.f, 0.f, 0.f);
        if (node < N_NODES) v = hin4[node * 16 + c];
        *(float4*)&sA[nodeLocal * A_STRIDE + c * 4] = v;
    }
    __syncwarp();

    // ---- GEMM2: acc += self @ Wr ----
#pragma unroll 4
    for (int k = 0; k < 64; k += 2) {
        float4 bv0 = *(const float4*)&sBr[k * 64 + hl * 4];
        float4 bv1 = *(const float4*)&sBr[(k + 1) * 64 + hl * 4];
        float2 a[7];
#pragma unroll
        for (int i = 0; i < 7; ++i)
            a[i] = *(const float2*)&sA[(rowBase + i) * A_STRIDE + k];
#pragma unroll
        for (int i = 0; i < 7; ++i) {
            acc[i][0] += a[i].x * bv0.x; acc[i][1] += a[i].x * bv0.y;
            acc[i][2] += a[i].x * bv0.z; acc[i][3] += a[i].x * bv0.w;
            acc[i][0] += a[i].y * bv1.x; acc[i][1] += a[i].y * bv1.y;
            acc[i][2] += a[i].y * bv1.z; acc[i][3] += a[i].y * bv1.w;
        }
    }

    if (!fuse_pool) {
        // ---- store h' ----
        float4* hout4 = (float4*)hout;
#pragma unroll
        for (int i = 0; i < 7; ++i) {
            int node = base + rowBase + i;
            if (node < N_NODES) {
                float4 o;
                o.x = acc[i][0]; o.y = acc[i][1]; o.z = acc[i][2]; o.w = acc[i][3];
                if (do_relu) {
                    o.x = fmaxf(o.x, 0.f); o.y = fmaxf(o.y, 0.f);
                    o.z = fmaxf(o.z, 0.f); o.w = fmaxf(o.w, 0.f);
                }
                hout4[node * 16 + hl] = o;
            }
        }
    } else {
        // ---- layer 3: pool directly (batch sorted -> run-accumulate) ----
        int cur = -1;
        float4 s = make_float4(0.f, 0.f, 0.f, 0.f);
#pragma unroll
        for (int i = 0; i < 7; ++i) {
            int node = base + rowBase + i;
            if (node < N_NODES) {
                int b = batch[node];
                if (b != cur) {
                    if (cur >= 0) {
                        float* dst = &g_pool[cur * 64 + hl * 4];
                        atomicAdd(dst + 0, s.x);
                        atomicAdd(dst + 1, s.y);
                        atomicAdd(dst + 2, s.z);
                        atomicAdd(dst + 3, s.w);
                    }
                    cur = b;
                    s = make_float4(0.f, 0.f, 0.f, 0.f);
                }
                s.x += acc[i][0]; s.y += acc[i][1];
                s.z += acc[i][2]; s.w += acc[i][3];
            }
        }
        if (cur >= 0) {
            float* dst = &g_pool[cur * 64 + hl * 4];
            atomicAdd(dst + 0, s.x);
            atomicAdd(dst + 1, s.y);
            atomicAdd(dst + 2, s.z);
            atomicAdd(dst + 3, s.w);
        }
    }
}

// ---------------- MLP head + state re-zero for next replay ----------------
__global__ void mlp_kernel(const float* __restrict__ Wc1,
                           const float* __restrict__ bc1,
                           const float* __restrict__ Wc2,
                           const float* __restrict__ bc2,
                           float* __restrict__ out) {
    int gr = blockIdx.x * 8 + (threadIdx.x >> 5);
    int lane = threadIdx.x & 31;
    if (gr < N_GRAPHS) {
        float h = bc1[lane];
#pragma unroll
        for (int k = 0; k < 64; ++k)
            h += g_pool[gr * 64 + k] * Wc1[k * 32 + lane];
        h = fmaxf(h, 0.0f);
        float p = h * Wc2[lane];
#pragma unroll
        for (int off = 16; off > 0; off >>= 1)
            p += __shfl_xor_sync(0xffffffffu, p, off);
        if (lane == 0) out[gr] = p + bc2[0];
        // zero own pool row for next replay (reads above are complete)
        g_pool[gr * 64 + 2 * lane]     = 0.0f;
        g_pool[gr * 64 + 2 * lane + 1] = 0.0f;
    }
    if (blockIdx.x == 0 && threadIdx.x == 0) g_bar = 0;  // reset scan barrier
}

// ---------------- launch ----------------
extern "C" void kernel_launch(void* const* d_in, const int* in_sizes, int n_in,
                              void* d_out, int out_size) {
    const float* x     = (const float*)d_in[0];
    const int*   edge  = (const int*)d_in[1];     // int32 (JAX x64 disabled)
    const int*   batch = (const int*)d_in[2];     // int32
    const float* W1l = (const float*)d_in[3];
    const float* b1  = (const float*)d_in[4];
    const float* W1r = (const float*)d_in[5];
    const float* W2l = (const float*)d_in[6];
    const float* b2  = (const float*)d_in[7];
    const float* W2r = (const float*)d_in[8];
    const float* W3l = (const float*)d_in[9];
    const float* b3  = (const float*)d_in[10];
    const float* W3r = (const float*)d_in[11];
    const float* Wc1 = (const float*)d_in[12];
    const float* bc1 = (const float*)d_in[13];
    const float* Wc2 = (const float*)d_in[14];
    const float* bc2 = (const float*)d_in[15];
    float* out = (float*)d_out;

    cudaFuncSetAttribute(sage64_kernel,
                         cudaFuncAttributeMaxDynamicSharedMemorySize, SM64_BYTES);

    count_kernel<<<(N_EDGES + 255) / 256, 256>>>(edge);            // 1
    scan_kernel<<<SCAN_BLOCKS, 1024>>>();                          // 2 (fused)
    fill_kernel<<<(N_EDGES + 255) / 256, 256>>>(edge);             // 3

    const int NT8  = (N_NODES + 127) / 128;                // 782
    const int NT64 = (N_NODES + TILE_N64 - 1) / TILE_N64;  // 893
    sage8_kernel<<<NT8, 256>>>(x, W1l, b1, W1r);                             // 4
    sage64_kernel<<<NT64, 256, SM64_BYTES>>>(0, W2l, b2, W2r, 1, 0, batch);  // 5
    sage64_kernel<<<NT64, 256, SM64_BYTES>>>(1, W3l, b3, W3r, 0, 1, batch);  // 6

    mlp_kernel<<<32, 256>>>(Wc1, bc1, Wc2, bc2, out);              // 7
}

// round 15
// speedup vs baseline: 1.3035x; 1.0628x over previous
#include <cuda_runtime.h>
#include <cuda_bf16.h>

#define N_NODES  100000
#define N_EDGES  1200000
#define N_GRAPHS 256
#define SCAN_BLOCKS 98   // ceil(100000/1024); MUST stay < 148 (co-resident)

// ---------------- device scratch (no allocs allowed) ----------------
// Contract: g_deg, g_poolM, g_poolS, g_cnt, g_bar are ZERO on entry to
// kernel_launch (zero-init on module load; scan_kernel re-zeroes g_deg,
// mlp_kernel re-zeroes the rest) -> deterministic graph replay.
__device__ int   g_deg[N_NODES];
__device__ int   g_rowptr[N_NODES + 1];
__device__ int   g_cur[N_NODES];
__device__ int   g_csr[N_EDGES];
__device__ int   g_bsums[SCAN_BLOCKS];
__device__ int   g_bar;
__device__ __align__(16) float g_h1[N_NODES * 64];
__device__ __align__(16) float g_h2[N_NODES * 64];
__device__ __align__(16) float g_poolM[N_GRAPHS * 64];  // sum of mean3 rows
__device__ __align__(16) float g_poolS[N_GRAPHS * 64];  // sum of h2 rows
__device__ int   g_cnt[N_GRAPHS];                       // nodes per graph

// ---------------- CSR build ----------------
__global__ void count_kernel(const int* __restrict__ edge) {
    int e = blockIdx.x * blockDim.x + threadIdx.x;
    if (e < N_EDGES) {
        int dst = edge[N_EDGES + e];
        atomicAdd(&g_deg[dst], 1);
    }
}

// Fused scan: per-block scan -> grid barrier (98 co-resident blocks) ->
// top-level prefix recomputed per block -> rowptr. Re-zeroes g_deg.
__global__ void scan_kernel() {
    __shared__ int s[1024];
    __shared__ int s2[128];
    const int tid = threadIdx.x;
    const int i = blockIdx.x * 1024 + tid;

    int v = (i < N_NODES) ? g_deg[i] : 0;
    s[tid] = v;
    __syncthreads();
    for (int off = 1; off < 1024; off <<= 1) {
        int t = (tid >= off) ? s[tid - off] : 0;
        __syncthreads();
        s[tid] += t;
        __syncthreads();
    }
    int local_excl = s[tid] - v;
    if (tid == 1023) g_bsums[blockIdx.x] = s[1023];

    __threadfence();
    __syncthreads();
    if (tid == 0) {
        atomicAdd(&g_bar, 1);
        while (*(volatile int*)&g_bar < SCAN_BLOCKS) { }
    }
    __syncthreads();
    __threadfence();

    if (tid < 128) s2[tid] = (tid < SCAN_BLOCKS) ? g_bsums[tid] : 0;
    __syncthreads();
    for (int off = 1; off < 128; off <<= 1) {
        int t = (tid < 128 && tid >= off) ? s2[tid - off] : 0;
        __syncthreads();
        if (tid < 128) s2[tid] += t;
        __syncthreads();
    }
    int boff = (blockIdx.x == 0) ? 0 : s2[blockIdx.x - 1];
    if (i < N_NODES) {
        int r = local_excl + boff;
        g_rowptr[i] = r;
        g_cur[i] = r;
        g_deg[i] = 0;
    }
    if (i == 0) g_rowptr[N_NODES] = N_EDGES;
}

__global__ void fill_kernel(const int* __restrict__ edge) {
    int e = blockIdx.x * blockDim.x + threadIdx.x;
    if (e < N_EDGES) {
        int src = edge[e];
        int dst = edge[N_EDGES + e];
        int pos = atomicAdd(&g_cur[dst], 1);
        g_csr[pos] = src;
    }
}

// ---------------- layer 1: x[100k,8] -> g_h1[100k,64], relu ----------------
#define A8_STRIDE 20
__global__ void sage8_kernel(const float* __restrict__ x,
                             const float* __restrict__ Wl,
                             const float* __restrict__ bias,
                             const float* __restrict__ Wr) {
    __shared__ __align__(16) float sA[128 * A8_STRIDE];
    __shared__ float sB[16 * 64];
    __shared__ float sBias[64];

    const int tid = threadIdx.x;
    if (tid < 128) ((float4*)sB)[tid] = ((const float4*)Wl)[tid];
    else           ((float4*)sB)[tid] = ((const float4*)Wr)[tid - 128];
    if (tid < 64) sBias[tid] = bias[tid];

    const int base = blockIdx.x * 128;
    const float4* x4 = (const float4*)x;

    {
        const int lane = tid & 31;
        const int nodeLocal = (tid >> 5) * 16 + (lane >> 1);
        const int p = lane & 1;
        const int node = base + nodeLocal;
        float4 m  = make_float4(0.f, 0.f, 0.f, 0.f);
        float4 sf = make_float4(0.f, 0.f, 0.f, 0.f);
        if (node < N_NODES) {
            int start = g_rowptr[node], end = g_rowptr[node + 1];
            float4 a0 = make_float4(0.f, 0.f, 0.f, 0.f);
            float4 a1 = make_float4(0.f, 0.f, 0.f, 0.f);
            float4 a2 = make_float4(0.f, 0.f, 0.f, 0.f);
            float4 a3 = make_float4(0.f, 0.f, 0.f, 0.f);
            int e = start;
            for (; e + 3 < end; e += 4) {
                int s0 = g_csr[e],     s1 = g_csr[e + 1];
                int s2 = g_csr[e + 2], s3 = g_csr[e + 3];
                float4 v0 = x4[s0 * 2 + p];
                float4 v1 = x4[s1 * 2 + p];
                float4 v2 = x4[s2 * 2 + p];
                float4 v3 = x4[s3 * 2 + p];
                a0.x += v0.x; a0.y += v0.y; a0.z += v0.z; a0.w += v0.w;
                a1.x += v1.x; a1.y += v1.y; a1.z += v1.z; a1.w += v1.w;
                a2.x += v2.x; a2.y += v2.y; a2.z += v2.z; a2.w += v2.w;
                a3.x += v3.x; a3.y += v3.y; a3.z += v3.z; a3.w += v3.w;
            }
            for (; e < end; ++e) {
                float4 v0 = x4[g_csr[e] * 2 + p];
                a0.x += v0.x; a0.y += v0.y; a0.z += v0.z; a0.w += v0.w;
            }
            float inv = 1.0f / (float)max(end - start, 1);
            m.x = (a0.x + a1.x + a2.x + a3.x) * inv;
            m.y = (a0.y + a1.y + a2.y + a3.y) * inv;
            m.z = (a0.z + a1.z + a2.z + a3.z) * inv;
            m.w = (a0.w + a1.w + a2.w + a3.w) * inv;
            sf = x4[node * 2 + p];
        }
        *(float4*)&sA[nodeLocal * A8_STRIDE + p * 4]     = m;
        *(float4*)&sA[nodeLocal * A8_STRIDE + 8 + p * 4] = sf;
    }
    __syncthreads();

    const int tn = tid & 15, tm = tid >> 4;
    float acc[8][4];
#pragma unroll
    for (int i = 0; i < 8; ++i)
#pragma unroll
        for (int j = 0; j < 4; ++j) acc[i][j] = sBias[tn * 4 + j];

#pragma unroll
    for (int k = 0; k < 16; ++k) {
        float4 bv = *(const float4*)&sB[k * 64 + tn * 4];
        float a[8];
#pragma unroll
        for (int i = 0; i < 8; ++i) a[i] = sA[(tm * 8 + i) * A8_STRIDE + k];
#pragma unroll
        for (int i = 0; i < 8; ++i) {
            acc[i][0] += a[i] * bv.x;
            acc[i][1] += a[i] * bv.y;
            acc[i][2] += a[i] * bv.z;
            acc[i][3] += a[i] * bv.w;
        }
    }

    float4* hout4 = (float4*)g_h1;
#pragma unroll
    for (int i = 0; i < 8; ++i) {
        int node = base + tm * 8 + i;
        if (node < N_NODES) {
            float4 o;
            o.x = fmaxf(acc[i][0], 0.0f);
            o.y = fmaxf(acc[i][1], 0.0f);
            o.z = fmaxf(acc[i][2], 0.0f);
            o.w = fmaxf(acc[i][3], 0.0f);
            hout4[node * 16 + tn] = o;
        }
    }
}

// ---------------- layer 2: g_h1 -> g_h2, relu (R8/R11 GEMM) ---------------
#define TILE_N64 112
#define A_STRIDE 68   // 272 B rows, 16B-aligned
#define SM64_BYTES ((TILE_N64 * A_STRIDE + 2 * 4096) * 4)   // 63232

__global__ void __launch_bounds__(256) sage64_kernel(
                              const float* __restrict__ Wl,
                              const float* __restrict__ bias,
                              const float* __restrict__ Wr) {
    extern __shared__ float sm64[];
    float* sA  = sm64;                              // [112][68]
    float* sBl = sm64 + TILE_N64 * A_STRIDE;        // [64][64]
    float* sBr = sBl + 4096;                        // [64][64]

    const float* hin = g_h1;
    float* hout      = g_h2;

    const int tid  = threadIdx.x;
    const int base = blockIdx.x * TILE_N64;
    const int warp = tid >> 5, lane = tid & 31;
    const int lr = lane >> 4;
    const int hl = lane & 15;

    {
        const float4* Wl4 = (const float4*)Wl;
        const float4* Wr4 = (const float4*)Wr;
        float4* l4 = (float4*)sBl;
        float4* r4 = (float4*)sBr;
#pragma unroll
        for (int t = 0; t < 4; ++t) {
            l4[tid + t * 256] = Wl4[tid + t * 256];
            r4[tid + t * 256] = Wr4[tid + t * 256];
        }
    }
    __syncthreads();

    const float4* hin4 = (const float4*)hin;
    const int rowBase = warp * 14 + lr * 7;

    for (int it = 0; it < 7; ++it) {
        int nodeLocal = rowBase + it;
        int node = base + nodeLocal;
        float4 m = make_float4(0.f, 0.f, 0.f, 0.f);
        if (node < N_NODES) {
            int start = g_rowptr[node], end = g_rowptr[node + 1];
            float4 a0 = make_float4(0.f, 0.f, 0.f, 0.f);
            float4 a1 = make_float4(0.f, 0.f, 0.f, 0.f);
            float4 a2 = make_float4(0.f, 0.f, 0.f, 0.f);
            float4 a3 = make_float4(0.f, 0.f, 0.f, 0.f);
            int e = start;
            for (; e + 3 < end; e += 4) {
                int s0 = g_csr[e],     s1 = g_csr[e + 1];
                int s2 = g_csr[e + 2], s3 = g_csr[e + 3];
                float4 v0 = hin4[s0 * 16 + hl];
                float4 v1 = hin4[s1 * 16 + hl];
                float4 v2 = hin4[s2 * 16 + hl];
                float4 v3 = hin4[s3 * 16 + hl];
                a0.x += v0.x; a0.y += v0.y; a0.z += v0.z; a0.w += v0.w;
                a1.x += v1.x; a1.y += v1.y; a1.z += v1.z; a1.w += v1.w;
                a2.x += v2.x; a2.y += v2.y; a2.z += v2.z; a2.w += v2.w;
                a3.x += v3.x; a3.y += v3.y; a3.z += v3.z; a3.w += v3.w;
            }
            for (; e < end; ++e) {
                int s0 = g_csr[e];
                float4 v0 = hin4[s0 * 16 + hl];
                a0.x += v0.x; a0.y += v0.y; a0.z += v0.z; a0.w += v0.w;
            }
            float inv = 1.0f / (float)max(end - start, 1);
            m.x = (a0.x + a1.x + a2.x + a3.x) * inv;
            m.y = (a0.y + a1.y + a2.y + a3.y) * inv;
            m.z = (a0.z + a1.z + a2.z + a3.z) * inv;
            m.w = (a0.w + a1.w + a2.w + a3.w) * inv;
        }
        *(float4*)&sA[nodeLocal * A_STRIDE + hl * 4] = m;
    }
    __syncwarp();

    float acc[7][4];
    {
        float4 bb = *(const float4*)&bias[hl * 4];
#pragma unroll
        for (int i = 0; i < 7; ++i) {
            acc[i][0] = bb.x; acc[i][1] = bb.y; acc[i][2] = bb.z; acc[i][3] = bb.w;
        }
    }

#pragma unroll 4
    for (int k = 0; k < 64; k += 2) {
        float4 bv0 = *(const float4*)&sBl[k * 64 + hl * 4];
        float4 bv1 = *(const float4*)&sBl[(k + 1) * 64 + hl * 4];
        float2 a[7];
#pragma unroll
        for (int i = 0; i < 7; ++i)
            a[i] = *(const float2*)&sA[(rowBase + i) * A_STRIDE + k];
#pragma unroll
        for (int i = 0; i < 7; ++i) {
            acc[i][0] += a[i].x * bv0.x; acc[i][1] += a[i].x * bv0.y;
            acc[i][2] += a[i].x * bv0.z; acc[i][3] += a[i].x * bv0.w;
            acc[i][0] += a[i].y * bv1.x; acc[i][1] += a[i].y * bv1.y;
            acc[i][2] += a[i].y * bv1.z; acc[i][3] += a[i].y * bv1.w;
        }
    }
    __syncwarp();

#pragma unroll
    for (int t = 0; t < 7; ++t) {
        int idx = lane + t * 32;
        int nl = idx >> 4, c = idx & 15;
        int nodeLocal = warp * 14 + nl;
        int node = base + nodeLocal;
        float4 v = make_float4(0.f, 0.f, 0.f, 0.f);
        if (node < N_NODES) v = hin4[node * 16 + c];
        *(float4*)&sA[nodeLocal * A_STRIDE + c * 4] = v;
    }
    __syncwarp();

#pragma unroll 4
    for (int k = 0; k < 64; k += 2) {
        float4 bv0 = *(const float4*)&sBr[k * 64 + hl * 4];
        float4 bv1 = *(const float4*)&sBr[(k + 1) * 64 + hl * 4];
        float2 a[7];
#pragma unroll
        for (int i = 0; i < 7; ++i)
            a[i] = *(const float2*)&sA[(rowBase + i) * A_STRIDE + k];
#pragma unroll
        for (int i = 0; i < 7; ++i) {
            acc[i][0] += a[i].x * bv0.x; acc[i][1] += a[i].x * bv0.y;
            acc[i][2] += a[i].x * bv0.z; acc[i][3] += a[i].x * bv0.w;
            acc[i][0] += a[i].y * bv1.x; acc[i][1] += a[i].y * bv1.y;
            acc[i][2] += a[i].y * bv1.z; acc[i][3] += a[i].y * bv1.w;
        }
    }

    float4* hout4 = (float4*)hout;
#pragma unroll
    for (int i = 0; i < 7; ++i) {
        int node = base + rowBase + i;
        if (node < N_NODES) {
            float4 o;
            o.x = fmaxf(acc[i][0], 0.f); o.y = fmaxf(acc[i][1], 0.f);
            o.z = fmaxf(acc[i][2], 0.f); o.w = fmaxf(acc[i][3], 0.f);
            hout4[node * 16 + hl] = o;
        }
    }
}

// ---------------- layer 3 (linear) + pool: gather-only --------------------
// g[graph] = (SUM mean3) @ W3l + (SUM h2) @ W3r + cnt*b3  -- GEMM deferred to
// mlp_kernel. Here: per-node neighbor-mean of g_h2 + own h2, run-accumulated
// per graph (batch sorted). Half-warp float4 lanes, 2 nodes in flight/warp.
__global__ void __launch_bounds__(256) pool3_kernel(const int* __restrict__ batch) {
    const int tid = threadIdx.x;
    const int base = blockIdx.x * 128;
    const int warp = tid >> 5, lane = tid & 31;
    const int half = lane >> 4, hl = lane & 15;
    const float4* hin4 = (const float4*)g_h2;

    int cur = -1, cnt = 0;
    float4 sM = make_float4(0.f, 0.f, 0.f, 0.f);
    float4 sS = make_float4(0.f, 0.f, 0.f, 0.f);

    for (int it = 0; it < 8; ++it) {
        int node = base + warp * 16 + it * 2 + half;
        if (node >= N_NODES) break;

        int start = g_rowptr[node], end = g_rowptr[node + 1];
        float4 a0 = make_float4(0.f, 0.f, 0.f, 0.f);
        float4 a1 = make_float4(0.f, 0.f, 0.f, 0.f);
        float4 a2 = make_float4(0.f, 0.f, 0.f, 0.f);
        float4 a3 = make_float4(0.f, 0.f, 0.f, 0.f);
        int e = start;
        for (; e + 3 < end; e += 4) {
            int s0 = g_csr[e],     s1 = g_csr[e + 1];
            int s2 = g_csr[e + 2], s3 = g_csr[e + 3];
            float4 v0 = hin4[s0 * 16 + hl];
            float4 v1 = hin4[s1 * 16 + hl];
            float4 v2 = hin4[s2 * 16 + hl];
            float4 v3 = hin4[s3 * 16 + hl];
            a0.x += v0.x; a0.y += v0.y; a0.z += v0.z; a0.w += v0.w;
            a1.x += v1.x; a1.y += v1.y; a1.z += v1.z; a1.w += v1.w;
            a2.x += v2.x; a2.y += v2.y; a2.z += v2.z; a2.w += v2.w;
            a3.x += v3.x; a3.y += v3.y; a3.z += v3.z; a3.w += v3.w;
        }
        for (; e < end; ++e) {
            float4 v0 = hin4[g_csr[e] * 16 + hl];
            a0.x += v0.x; a0.y += v0.y; a0.z += v0.z; a0.w += v0.w;
        }
        float inv = 1.0f / (float)max(end - start, 1);
        float4 m;
        m.x = (a0.x + a1.x + a2.x + a3.x) * inv;
        m.y = (a0.y + a1.y + a2.y + a3.y) * inv;
        m.z = (a0.z + a1.z + a2.z + a3.z) * inv;
        m.w = (a0.w + a1.w + a2.w + a3.w) * inv;
        float4 sf = hin4[node * 16 + hl];

        int b = batch[node];
        if (b != cur) {
            if (cur >= 0) {
                float* dM = &g_poolM[cur * 64 + hl * 4];
                float* dS = &g_poolS[cur * 64 + hl * 4];
                atomicAdd(dM + 0, sM.x); atomicAdd(dM + 1, sM.y);
                atomicAdd(dM + 2, sM.z); atomicAdd(dM + 3, sM.w);
                atomicAdd(dS + 0, sS.x); atomicAdd(dS + 1, sS.y);
                atomicAdd(dS + 2, sS.z); atomicAdd(dS + 3, sS.w);
                if (hl == 0) atomicAdd(&g_cnt[cur], cnt);
            }
            cur = b; cnt = 0;
            sM = make_float4(0.f, 0.f, 0.f, 0.f);
            sS = make_float4(0.f, 0.f, 0.f, 0.f);
        }
        sM.x += m.x; sM.y += m.y; sM.z += m.z; sM.w += m.w;
        sS.x += sf.x; sS.y += sf.y; sS.z += sf.z; sS.w += sf.w;
        ++cnt;
    }
    if (cur >= 0) {
        float* dM = &g_poolM[cur * 64 + hl * 4];
        float* dS = &g_poolS[cur * 64 + hl * 4];
        atomicAdd(dM + 0, sM.x); atomicAdd(dM + 1, sM.y);
        atomicAdd(dM + 2, sM.z); atomicAdd(dM + 3, sM.w);
        atomicAdd(dS + 0, sS.x); atomicAdd(dS + 1, sS.y);
        atomicAdd(dS + 2, sS.z); atomicAdd(dS + 3, sS.w);
        if (hl == 0) atomicAdd(&g_cnt[cur], cnt);
    }
}

// ---------------- MLP head: layer-3 GEMM on pooled vectors + classifier ---
// Warp per graph: h3[64] = poolM@W3l + poolS@W3r + cnt*b3; relu(h3@Wc1+bc1);
// out = .@Wc2 + bc2. Re-zeroes g_poolM/g_poolS/g_cnt/g_bar for next replay.
__global__ void mlp_kernel(const float* __restrict__ W3l,
                           const float* __restrict__ b3,
                           const float* __restrict__ W3r,
                           const float* __restrict__ Wc1,
                           const float* __restrict__ bc1,
                           const float* __restrict__ Wc2,
                           const float* __restrict__ bc2,
                           float* __restrict__ out) {
    __shared__ float sh[8][64];
    int warp = threadIdx.x >> 5;
    int lane = threadIdx.x & 31;
    int gr = blockIdx.x * 8 + warp;
    if (gr < N_GRAPHS) {
        float c = (float)g_cnt[gr];
        float h0 = c * b3[2 * lane];
        float h1 = c * b3[2 * lane + 1];
#pragma unroll 4
        for (int k = 0; k < 64; ++k) {
            float pm = g_poolM[gr * 64 + k];
            float ps = g_poolS[gr * 64 + k];
            h0 += pm * W3l[k * 64 + 2 * lane]     + ps * W3r[k * 64 + 2 * lane];
            h1 += pm * W3l[k * 64 + 2 * lane + 1] + ps * W3r[k * 64 + 2 * lane + 1];
        }
        sh[warp][2 * lane]     = h0;
        sh[warp][2 * lane + 1] = h1;
        __syncwarp();
        float h = bc1[lane];
#pragma unroll
        for (int k = 0; k < 64; ++k)
            h += sh[warp][k] * Wc1[k * 32 + lane];
        h = fmaxf(h, 0.0f);
        float p = h * Wc2[lane];
#pragma unroll
        for (int off = 16; off > 0; off >>= 1)
            p += __shfl_xor_sync(0xffffffffu, p, off);
        if (lane == 0) out[gr] = p + bc2[0];
        // re-zero replay state (own graph's rows; reads above complete)
        g_poolM[gr * 64 + 2 * lane]     = 0.0f;
        g_poolM[gr * 64 + 2 * lane + 1] = 0.0f;
        g_poolS[gr * 64 + 2 * lane]     = 0.0f;
        g_poolS[gr * 64 + 2 * lane + 1] = 0.0f;
        if (lane == 0) g_cnt[gr] = 0;
    }
    if (blockIdx.x == 0 && threadIdx.x == 0) g_bar = 0;
}

// ---------------- launch ----------------
extern "C" void kernel_launch(void* const* d_in, const int* in_sizes, int n_in,
                              void* d_out, int out_size) {
    const float* x     = (const float*)d_in[0];
    const int*   edge  = (const int*)d_in[1];     // int32 (JAX x64 disabled)
    const int*   batch = (const int*)d_in[2];     // int32
    const float* W1l = (const float*)d_in[3];
    const float* b1  = (const float*)d_in[4];
    const float* W1r = (const float*)d_in[5];
    const float* W2l = (const float*)d_in[6];
    const float* b2  = (const float*)d_in[7];
    const float* W2r = (const float*)d_in[8];
    const float* W3l = (const float*)d_in[9];
    const float* b3  = (const float*)d_in[10];
    const float* W3r = (const float*)d_in[11];
    const float* Wc1 = (const float*)d_in[12];
    const float* bc1 = (const float*)d_in[13];
    const float* Wc2 = (const float*)d_in[14];
    const float* bc2 = (const float*)d_in[15];
    float* out = (float*)d_out;

    cudaFuncSetAttribute(sage64_kernel,
                         cudaFuncAttributeMaxDynamicSharedMemorySize, SM64_BYTES);

    count_kernel<<<(N_EDGES + 255) / 256, 256>>>(edge);            // 1
    scan_kernel<<<SCAN_BLOCKS, 1024>>>();                          // 2
    fill_kernel<<<(N_EDGES + 255) / 256, 256>>>(edge);             // 3

    const int NT8  = (N_NODES + 127) / 128;                // 782
    const int NT64 = (N_NODES + TILE_N64 - 1) / TILE_N64;  // 893
    sage8_kernel<<<NT8, 256>>>(x, W1l, b1, W1r);                   // 4
    sage64_kernel<<<NT64, 256, SM64_BYTES>>>(W2l, b2, W2r);        // 5
    pool3_kernel<<<NT8, 256>>>(batch);                             // 6

    mlp_kernel<<<32, 256>>>(W3l, b3, W3r, Wc1, bc1, Wc2, bc2, out);// 7
}